// round 16
// baseline (speedup 1.0000x reference)
#include <cuda_runtime.h>
#include <cuda_fp16.h>
#include <cstdint>

#define N_OBJ  20000
#define N_ROOM 500
#define N_ATTR 2000
#define IN_F   300
#define HDIM   512
#define EOO    640000
#define ERO    50000
#define EAO    100000
#define BATCH  8

#define MP   20096
#define KP1  320           // conv1 K padded to 32-multiple
#define KP2  512
#define TT1  30            // 3 relations * 10 chunks of BK=32
#define TT2  16            // 512/32

// ---------------- scratch (device globals, no allocation) ----------------
__device__ __half g_hs[(size_t)N_OBJ * HDIM];     // fp16 h_obj * ns_oo

__device__ __half g_fo16[(size_t)N_OBJ  * IN_F];  // fp16 feature tables
__device__ __half g_fr16[(size_t)N_ROOM * IN_F];
__device__ __half g_fa16[(size_t)N_ATTR * IN_F];

__device__ int g_dout_oo[N_OBJ];
__device__ int g_din_oo [N_OBJ];
__device__ int g_dout_ro[N_ROOM];
__device__ int g_din_ro [N_OBJ];
__device__ int g_dout_ao[N_ATTR];
__device__ int g_din_ao [N_OBJ];

__device__ int g_off_oo[N_OBJ + 1];
__device__ int g_off_ro[N_OBJ + 1];
__device__ int g_off_ao[N_OBJ + 1];
__device__ int g_cnt_oo[N_OBJ];
__device__ int g_cnt_ro[N_OBJ];
__device__ int g_cnt_ao[N_OBJ];
__device__ int g_csr_oo[EOO];
__device__ int g_csr_ro[ERO];
__device__ int g_csr_ao[EAO];

__device__ __half g_A1[3][(size_t)MP * KP1];      // single fp16 activations
__device__ __half g_A2[(size_t)MP * KP2];
__device__ __half g_W[3][(size_t)KP2 * HDIM];     // 0:W1i 1:W1b 2:W2

// ---------------- prep: zero degs + pads + fp16 converts ----------
__global__ void prep(const float* __restrict__ W1i, const float* __restrict__ W1b,
                     const float* __restrict__ W2,
                     const float* __restrict__ fo, const float* __restrict__ fr,
                     const float* __restrict__ fa) {
    int tid    = blockIdx.x * blockDim.x + threadIdx.x;
    int stride = gridDim.x * blockDim.x;
    for (int i = tid; i < N_OBJ; i += stride) {
        g_dout_oo[i] = 0; g_din_oo[i] = 0; g_din_ro[i] = 0; g_din_ao[i] = 0;
    }
    for (int i = tid; i < N_ROOM; i += stride) g_dout_ro[i] = 0;
    for (int i = tid; i < N_ATTR; i += stride) g_dout_ao[i] = 0;
    const __half z = __float2half(0.f);
    // K-pad cols 304..319 (agg1 writes only 0..303)
    for (int i = tid; i < MP * 16; i += stride) {
        int r = i / 16, c = 304 + (i % 16);
        size_t o = (size_t)r * KP1 + c;
        g_A1[0][o] = z; g_A1[1][o] = z; g_A1[2][o] = z;
    }
    int padA1 = (MP - N_OBJ) * KP1;
    for (int i = tid; i < padA1; i += stride) {
        size_t o = (size_t)N_OBJ * KP1 + i;
        g_A1[0][o] = z; g_A1[1][o] = z; g_A1[2][o] = z;
    }
    int padA2 = (MP - N_OBJ) * KP2;
    for (int i = tid; i < padA2; i += stride)
        g_A2[(size_t)N_OBJ * KP2 + i] = z;

    const int n1 = KP1 * HDIM;
    for (int idx = tid; idx < n1; idx += stride) {
        int r = idx / HDIM;
        g_W[0][idx] = __float2half_rn((r < IN_F) ? W1i[idx] : 0.f);
        g_W[1][idx] = __float2half_rn((r < IN_F) ? W1b[idx] : 0.f);
    }
    const int n2 = KP2 * HDIM;
    for (int idx = tid; idx < n2; idx += stride)
        g_W[2][idx] = __float2half_rn(W2[idx]);

    const int nfo = N_OBJ * IN_F;
    for (int idx = tid; idx < nfo; idx += stride) g_fo16[idx] = __float2half_rn(fo[idx]);
    const int nfr = N_ROOM * IN_F;
    for (int idx = tid; idx < nfr; idx += stride) g_fr16[idx] = __float2half_rn(fr[idx]);
    const int nfa = N_ATTR * IN_F;
    for (int idx = tid; idx < nfa; idx += stride) g_fa16[idx] = __float2half_rn(fa[idx]);
}

// ---------------- merged degree counting ----------------
__global__ void deg_all(const int* __restrict__ src_oo, const int* __restrict__ dst_oo,
                        const int* __restrict__ src_ro, const int* __restrict__ dst_ro,
                        const int* __restrict__ src_ao, const int* __restrict__ dst_ao) {
    int i = blockIdx.x * blockDim.x + threadIdx.x;
    if (i < EOO) {
        atomicAdd(&g_dout_oo[src_oo[i]], 1);
        atomicAdd(&g_din_oo [dst_oo[i]], 1);
    } else if (i < EOO + ERO) {
        int j = i - EOO;
        atomicAdd(&g_dout_ro[src_ro[j]], 1);
        atomicAdd(&g_din_ro [dst_ro[j]], 1);
    } else if (i < EOO + ERO + EAO) {
        int j = i - EOO - ERO;
        atomicAdd(&g_dout_ao[src_ao[j]], 1);
        atomicAdd(&g_din_ao [dst_ao[j]], 1);
    }
}

// ---------------- 3-block exclusive scan ----------------
__global__ void scan3() {
    int sel = blockIdx.x;
    const int* deg = (sel == 0) ? g_din_oo : (sel == 1) ? g_din_ro : g_din_ao;
    int* offs      = (sel == 0) ? g_off_oo : (sel == 1) ? g_off_ro : g_off_ao;
    int* cnt       = (sel == 0) ? g_cnt_oo : (sel == 1) ? g_cnt_ro : g_cnt_ao;
    __shared__ int part[1025];
    const int n = N_OBJ;
    int t = threadIdx.x;
    int chunk = (n + 1023) / 1024;
    int b = t * chunk, e = min(b + chunk, n);
    int s = 0;
    for (int i = b; i < e; i++) s += deg[i];
    part[t + 1] = s;
    if (t == 0) part[0] = 0;
    __syncthreads();
    for (int off = 1; off < 1024; off <<= 1) {
        int v = part[t + 1];
        if (t + 1 > off) v += part[t + 1 - off];
        __syncthreads();
        part[t + 1] = v;
        __syncthreads();
    }
    int run = part[t];
    for (int i = b; i < e; i++) { offs[i] = run; cnt[i] = run; run += deg[i]; }
    if (t == 0) offs[n] = part[1024];
}

// ---------------- merged edge scatter ----------------
__global__ void scatter_all(const int* __restrict__ src_oo, const int* __restrict__ dst_oo,
                            const int* __restrict__ src_ro, const int* __restrict__ dst_ro,
                            const int* __restrict__ src_ao, const int* __restrict__ dst_ao) {
    int i = blockIdx.x * blockDim.x + threadIdx.x;
    if (i < EOO) {
        int pos = atomicAdd(&g_cnt_oo[dst_oo[i]], 1);
        g_csr_oo[pos] = src_oo[i];
    } else if (i < EOO + ERO) {
        int j = i - EOO;
        int pos = atomicAdd(&g_cnt_ro[dst_ro[j]], 1);
        g_csr_ro[pos] = src_ro[j];
    } else if (i < EOO + ERO + EAO) {
        int j = i - EOO - ERO;
        int pos = atomicAdd(&g_cnt_ao[dst_ao[j]], 1);
        g_csr_ao[pos] = src_ao[j];
    }
}

// ---------------- conv1 aggregation (fp16 features, fp32 accum), chunked ----
__global__ void __launch_bounds__(128) agg1_all(int row_base) {
    int sel = blockIdx.y;
    const __half* feat = (sel == 0) ? g_fo16 : (sel == 1) ? g_fr16 : g_fa16;
    const int* offs   = (sel == 0) ? g_off_oo  : (sel == 1) ? g_off_ro  : g_off_ao;
    const int* csr    = (sel == 0) ? g_csr_oo  : (sel == 1) ? g_csr_ro  : g_csr_ao;
    const int* degout = (sel == 0) ? g_dout_oo : (sel == 1) ? g_dout_ro : g_dout_ao;
    __half* A = g_A1[sel];

    int row = row_base + blockIdx.x;
    int t = threadIdx.x;
    int beg = offs[row], end = offs[row + 1];
    float4 a = make_float4(0.f, 0.f, 0.f, 0.f);
    __shared__ int   ss[128];
    __shared__ float sn[128];

    const int NV = IN_F / 4;            // 75
    for (int base = beg; base < end; base += 128) {
        int nB = min(128, end - base);
        __syncthreads();
        if (t < nB) {
            int s = csr[base + t];
            ss[t] = s;
            sn[t] = rsqrtf((float)max(degout[s], 1));
        }
        __syncthreads();
        int j = 0;
        if (t < NV) {
            for (; j + 4 <= nB; j += 4) {
                const uint2* p0 = (const uint2*)(feat + (size_t)ss[j + 0] * IN_F);
                const uint2* p1 = (const uint2*)(feat + (size_t)ss[j + 1] * IN_F);
                const uint2* p2 = (const uint2*)(feat + (size_t)ss[j + 2] * IN_F);
                const uint2* p3 = (const uint2*)(feat + (size_t)ss[j + 3] * IN_F);
                uint2 u0 = p0[t], u1 = p1[t], u2 = p2[t], u3 = p3[t];
                float n0 = sn[j], n1 = sn[j + 1], n2 = sn[j + 2], n3 = sn[j + 3];
                float2 c0 = __half22float2(*(__half2*)&u0.x), d0 = __half22float2(*(__half2*)&u0.y);
                float2 c1 = __half22float2(*(__half2*)&u1.x), d1 = __half22float2(*(__half2*)&u1.y);
                float2 c2 = __half22float2(*(__half2*)&u2.x), d2 = __half22float2(*(__half2*)&u2.y);
                float2 c3 = __half22float2(*(__half2*)&u3.x), d3 = __half22float2(*(__half2*)&u3.y);
                a.x += c0.x * n0 + c1.x * n1 + c2.x * n2 + c3.x * n3;
                a.y += c0.y * n0 + c1.y * n1 + c2.y * n2 + c3.y * n3;
                a.z += d0.x * n0 + d1.x * n1 + d2.x * n2 + d3.x * n3;
                a.w += d0.y * n0 + d1.y * n1 + d2.y * n2 + d3.y * n3;
            }
            for (; j < nB; j++) {
                uint2 u = ((const uint2*)(feat + (size_t)ss[j] * IN_F))[t];
                float n = sn[j];
                float2 c = __half22float2(*(__half2*)&u.x), d = __half22float2(*(__half2*)&u.y);
                a.x += c.x * n; a.y += c.y * n; a.z += d.x * n; a.w += d.y * n;
            }
        }
    }

    if (t <= NV) {
        if (t == NV) a = make_float4(0.f, 0.f, 0.f, 0.f);
        size_t o = (size_t)row * KP1 + t * 4;
        *(__half2*)(A + o)     = __floats2half2_rn(a.x, a.y);
        *(__half2*)(A + o + 2) = __floats2half2_rn(a.z, a.w);
    }
}

// ---------------- conv2 aggregation (fp16 g_hs, fp32 accum), chunked --------
__global__ void __launch_bounds__(128) agg2(int row_base) {
    int row = row_base + blockIdx.x;
    int t = threadIdx.x;
    int beg = g_off_oo[row], end = g_off_oo[row + 1];
    float4 a = make_float4(0.f, 0.f, 0.f, 0.f);
    __shared__ int ss[128];

    for (int base = beg; base < end; base += 128) {
        int nB = min(128, end - base);
        __syncthreads();
        if (t < nB) ss[t] = g_csr_oo[base + t];
        __syncthreads();
        int j = 0;
        for (; j + 4 <= nB; j += 4) {
            const uint2* p0 = (const uint2*)(g_hs + (size_t)ss[j + 0] * HDIM);
            const uint2* p1 = (const uint2*)(g_hs + (size_t)ss[j + 1] * HDIM);
            const uint2* p2 = (const uint2*)(g_hs + (size_t)ss[j + 2] * HDIM);
            const uint2* p3 = (const uint2*)(g_hs + (size_t)ss[j + 3] * HDIM);
            uint2 u0 = p0[t], u1 = p1[t], u2 = p2[t], u3 = p3[t];
            float2 c0 = __half22float2(*(__half2*)&u0.x), d0 = __half22float2(*(__half2*)&u0.y);
            float2 c1 = __half22float2(*(__half2*)&u1.x), d1 = __half22float2(*(__half2*)&u1.y);
            float2 c2 = __half22float2(*(__half2*)&u2.x), d2 = __half22float2(*(__half2*)&u2.y);
            float2 c3 = __half22float2(*(__half2*)&u3.x), d3 = __half22float2(*(__half2*)&u3.y);
            a.x += c0.x + c1.x + c2.x + c3.x;
            a.y += c0.y + c1.y + c2.y + c3.y;
            a.z += d0.x + d1.x + d2.x + d3.x;
            a.w += d0.y + d1.y + d2.y + d3.y;
        }
        for (; j < nB; j++) {
            uint2 u = ((const uint2*)(g_hs + (size_t)ss[j] * HDIM))[t];
            float2 c = __half22float2(*(__half2*)&u.x), d = __half22float2(*(__half2*)&u.y);
            a.x += c.x; a.y += c.y; a.z += d.x; a.w += d.y;
        }
    }

    size_t o = (size_t)row * KP2 + t * 4;
    *(__half2*)(g_A2 + o)     = __floats2half2_rn(a.x, a.y);
    *(__half2*)(g_A2 + o + 2) = __floats2half2_rn(a.z, a.w);
}

// ---------------- GEMM primitives ----------------
__device__ __forceinline__ void cpasync16(void* smem_dst, const void* gmem_src) {
    uint32_t sa = (uint32_t)__cvta_generic_to_shared(smem_dst);
    asm volatile("cp.async.cg.shared.global [%0], [%1], 16;\n" :: "r"(sa), "l"(gmem_src));
}
__device__ __forceinline__ void cp_commit() { asm volatile("cp.async.commit_group;\n" ::: "memory"); }
template <int N>
__device__ __forceinline__ void cp_wait() { asm volatile("cp.async.wait_group %0;\n" :: "n"(N) : "memory"); }

__device__ __forceinline__ void ldsm4(uint32_t* r, const void* p) {
    uint32_t a = (uint32_t)__cvta_generic_to_shared(p);
    asm volatile("ldmatrix.sync.aligned.m8n8.x4.shared.b16 {%0,%1,%2,%3}, [%4];\n"
                 : "=r"(r[0]), "=r"(r[1]), "=r"(r[2]), "=r"(r[3]) : "r"(a));
}
__device__ __forceinline__ void ldsm4t(uint32_t* r, const void* p) {
    uint32_t a = (uint32_t)__cvta_generic_to_shared(p);
    asm volatile("ldmatrix.sync.aligned.m8n8.x4.trans.shared.b16 {%0,%1,%2,%3}, [%4];\n"
                 : "=r"(r[0]), "=r"(r[1]), "=r"(r[2]), "=r"(r[3]) : "r"(a));
}
__device__ __forceinline__ void mma_fp16(float* d, const uint32_t* a, uint32_t b0, uint32_t b1) {
    asm volatile("mma.sync.aligned.m16n8k16.row.col.f32.f16.f16.f32 "
                 "{%0,%1,%2,%3}, {%4,%5,%6,%7}, {%8,%9}, {%0,%1,%2,%3};\n"
                 : "+f"(d[0]), "+f"(d[1]), "+f"(d[2]), "+f"(d[3])
                 : "r"(a[0]), "r"(a[1]), "r"(a[2]), "r"(a[3]), "r"(b0), "r"(b1));
}

// smem stage types
typedef __half (*SA1_t)[64][40];      // gemm1: [stage][m=64][kpad 40]
typedef __half (*SA2_t)[128][40];     // gemm2: [stage][m=128][kpad 40]
typedef __half (*SB_t)[32][136];      // [stage][k][npad]
#define SMEM_A1_BYTES (3 * 64 * 40 * 2)
#define SMEM_A2_BYTES (3 * 128 * 40 * 2)
#define SMEM_B_BYTES  (3 * 32 * 136 * 2)
#define SMEM1_BYTES   (SMEM_A1_BYTES + SMEM_B_BYTES)
#define SMEM2_BYTES   (SMEM_A2_BYTES + SMEM_B_BYTES)

// ---------------- merged conv1 GEMM (64x128 tile, occupancy 2), chunked ----
// hs = (sum_rel relu(A_rel@W+b)/3) * ns_oo
__global__ void __launch_bounds__(256, 2) gemm1(const float* __restrict__ b1i,
                                                const float* __restrict__ b1b,
                                                int row_base) {
    extern __shared__ __align__(16) char smem[];
    SA1_t sA = (SA1_t)smem;
    SB_t  sB = (SB_t)(smem + SMEM_A1_BYTES);

    int tid = threadIdx.x;
    int warp = tid >> 5, lane = tid & 31;
    int row0 = row_base + blockIdx.y * 64, col0 = blockIdx.x * 128;
    int wr = warp >> 2, wc = warp & 3;   // 2x4 warps, warp tile 32x32

    float acc[2][4][4] = {};
    float accsum[2][4][4] = {};

    int aR = tid >> 2, aC = tid & 3;
    int bR = tid >> 4, bC = tid & 15;

    auto load_stage = [&](int t, int s) {
        int rel = t / 10;
        int tt  = t % 10;
        int wsel = (rel == 2) ? 1 : 0;
        const __half* Ap = g_A1[rel];
        int kb = tt * 32;
        cpasync16(&sA[s][aR][aC * 8],
                  Ap + (size_t)(row0 + aR) * KP1 + kb + aC * 8);
        #pragma unroll
        for (int rr = 0; rr < 2; rr++)
            cpasync16(&sB[s][bR + rr * 16][bC * 8],
                      g_W[wsel] + (size_t)(kb + bR + rr * 16) * HDIM + col0 + bC * 8);
    };

    load_stage(0, 0); cp_commit();
    load_stage(1, 1); cp_commit();

    int s = 0;
    for (int t = 0; t < TT1; t++) {
        cp_wait<1>();
        __syncthreads();
        int tp = t + 2;
        if (tp < TT1) load_stage(tp, tp % 3);
        cp_commit();

        int arow = wr * 32 + (lane & 15);
        int acol8 = (lane >> 4) * 8;
        int brow = lane & 15;
        int bcol = wc * 32 + (lane >> 4) * 8;
        #pragma unroll
        for (int ksub = 0; ksub < 2; ksub++) {
            uint32_t aa[2][4], bb[2][4];
            #pragma unroll
            for (int m = 0; m < 2; m++)
                ldsm4(aa[m], &sA[s][arow + m * 16][ksub * 16 + acol8]);
            #pragma unroll
            for (int p = 0; p < 2; p++)
                ldsm4t(bb[p], &sB[s][ksub * 16 + brow][bcol + p * 16]);
            #pragma unroll
            for (int m = 0; m < 2; m++)
                #pragma unroll
                for (int n = 0; n < 4; n++) {
                    int p = n >> 1, h = n & 1;
                    mma_fp16(acc[m][n], aa[m], bb[p][h * 2], bb[p][h * 2 + 1]);
                }
        }

        if (t % 10 == 9) {
            int rel = t / 10;
            const int* degin = (rel == 0) ? g_din_oo : (rel == 1) ? g_din_ro : g_din_ao;
            const float* bias = (rel == 2) ? b1b : b1i;
            const float third = 1.f / 3.f;
            #pragma unroll
            for (int m = 0; m < 2; m++) {
                int r1 = row0 + wr * 32 + m * 16 + (lane >> 2);
                int r2 = r1 + 8;
                float nd1 = (r1 < N_OBJ) ? rsqrtf((float)max(degin[r1], 1)) : 0.f;
                float nd2 = (r2 < N_OBJ) ? rsqrtf((float)max(degin[r2], 1)) : 0.f;
                #pragma unroll
                for (int n = 0; n < 4; n++) {
                    int c = col0 + wc * 32 + n * 8 + (lane & 3) * 2;
                    float bx = bias[c], by = bias[c + 1];
                    accsum[m][n][0] += fmaxf(acc[m][n][0] * nd1 + bx, 0.f) * third;
                    accsum[m][n][1] += fmaxf(acc[m][n][1] * nd1 + by, 0.f) * third;
                    accsum[m][n][2] += fmaxf(acc[m][n][2] * nd2 + bx, 0.f) * third;
                    accsum[m][n][3] += fmaxf(acc[m][n][3] * nd2 + by, 0.f) * third;
                    acc[m][n][0] = 0.f; acc[m][n][1] = 0.f;
                    acc[m][n][2] = 0.f; acc[m][n][3] = 0.f;
                }
            }
        }
        s++; if (s == 3) s = 0;
    }

    // final write: hs = accsum * ns_oo  (fp16)
    #pragma unroll
    for (int m = 0; m < 2; m++) {
        int r1 = row0 + wr * 32 + m * 16 + (lane >> 2);
        int r2 = r1 + 8;
        float sc1 = (r1 < N_OBJ) ? rsqrtf((float)max(g_dout_oo[r1], 1)) : 0.f;
        float sc2 = (r2 < N_OBJ) ? rsqrtf((float)max(g_dout_oo[r2], 1)) : 0.f;
        #pragma unroll
        for (int n = 0; n < 4; n++) {
            int c = col0 + wc * 32 + n * 8 + (lane & 3) * 2;
            if (r1 < N_OBJ)
                *(__half2*)(g_hs + (size_t)r1 * HDIM + c) =
                    __floats2half2_rn(accsum[m][n][0] * sc1, accsum[m][n][1] * sc1);
            if (r2 < N_OBJ)
                *(__half2*)(g_hs + (size_t)r2 * HDIM + c) =
                    __floats2half2_rn(accsum[m][n][2] * sc2, accsum[m][n][3] * sc2);
        }
    }
}

// ---------------- conv2 GEMM (128x128, occ 2), chunked: out = A2@W2*nd + b2 --
__global__ void __launch_bounds__(256, 2) gemm2(const float* __restrict__ bias,
                                                float* __restrict__ outp,
                                                int row_base) {
    extern __shared__ __align__(16) char smem[];
    SA2_t sA = (SA2_t)smem;
    SB_t  sB = (SB_t)(smem + SMEM_A2_BYTES);

    int tid = threadIdx.x;
    int warp = tid >> 5, lane = tid & 31;
    int row0 = row_base + blockIdx.y * 128, col0 = blockIdx.x * 128;
    int wr = warp >> 2, wc = warp & 3;

    float acc[4][4][4] = {};

    int aR = tid >> 2, aC = tid & 3;
    int bR = tid >> 4, bC = tid & 15;

    auto load_stage = [&](int t, int s) {
        int kb = t * 32;
        #pragma unroll
        for (int rr = 0; rr < 2; rr++) {
            cpasync16(&sA[s][aR + rr * 64][aC * 8],
                      g_A2 + (size_t)(row0 + aR + rr * 64) * KP2 + kb + aC * 8);
            cpasync16(&sB[s][bR + rr * 16][bC * 8],
                      g_W[2] + (size_t)(kb + bR + rr * 16) * HDIM + col0 + bC * 8);
        }
    };

    load_stage(0, 0); cp_commit();
    load_stage(1, 1); cp_commit();

    int s = 0;
    for (int t = 0; t < TT2; t++) {
        cp_wait<1>();
        __syncthreads();
        int tp = t + 2;
        if (tp < TT2) load_stage(tp, tp % 3);
        cp_commit();

        int arow = wr * 64 + (lane & 15);
        int acol8 = (lane >> 4) * 8;
        int brow = lane & 15;
        int bcol = wc * 32 + (lane >> 4) * 8;
        #pragma unroll
        for (int ksub = 0; ksub < 2; ksub++) {
            uint32_t aa[4][4], bb[2][4];
            #pragma unroll
            for (int m = 0; m < 4; m++)
                ldsm4(aa[m], &sA[s][arow + m * 16][ksub * 16 + acol8]);
            #pragma unroll
            for (int p = 0; p < 2; p++)
                ldsm4t(bb[p], &sB[s][ksub * 16 + brow][bcol + p * 16]);
            #pragma unroll
            for (int m = 0; m < 4; m++)
                #pragma unroll
                for (int n = 0; n < 4; n++) {
                    int p = n >> 1, h = n & 1;
                    mma_fp16(acc[m][n], aa[m], bb[p][h * 2], bb[p][h * 2 + 1]);
                }
        }
        s++; if (s == 3) s = 0;
    }

    #pragma unroll
    for (int m = 0; m < 4; m++) {
        int r1 = row0 + wr * 64 + m * 16 + (lane >> 2);
        int r2 = r1 + 8;
        float nd1 = (r1 < N_OBJ) ? rsqrtf((float)max(g_din_oo[r1], 1)) : 0.f;
        float nd2 = (r2 < N_OBJ) ? rsqrtf((float)max(g_din_oo[r2], 1)) : 0.f;
        #pragma unroll
        for (int n = 0; n < 4; n++) {
            int c = col0 + wc * 32 + n * 8 + (lane & 3) * 2;
            float bx = bias[c], by = bias[c + 1];
            float v1x = acc[m][n][0] * nd1 + bx;
            float v1y = acc[m][n][1] * nd1 + by;
            float v2x = acc[m][n][2] * nd2 + bx;
            float v2y = acc[m][n][3] * nd2 + by;
            #pragma unroll
            for (int b = 0; b < BATCH; b++) {
                if (r1 < N_OBJ)
                    *(float2*)(outp + (size_t)b * N_OBJ * HDIM + (size_t)r1 * HDIM + c) =
                        make_float2(v1x, v1y);
                if (r2 < N_OBJ)
                    *(float2*)(outp + (size_t)b * N_OBJ * HDIM + (size_t)r2 * HDIM + c) =
                        make_float2(v2x, v2y);
            }
        }
    }
}

// ---------------- launch ----------------
extern "C" void kernel_launch(void* const* d_in, const int* in_sizes, int n_in,
                              void* d_out, int out_size) {
    const float* feat_obj  = (const float*)d_in[1];
    const float* feat_room = (const float*)d_in[2];
    const float* feat_attr = (const float*)d_in[3];
    const float* W1i = (const float*)d_in[4];
    const float* b1i = (const float*)d_in[5];
    const float* W1b = (const float*)d_in[6];
    const float* b1b = (const float*)d_in[7];
    const float* W2  = (const float*)d_in[8];
    const float* b2  = (const float*)d_in[9];
    const int* src_oo = (const int*)d_in[10];
    const int* dst_oo = (const int*)d_in[11];
    const int* src_ro = (const int*)d_in[12];
    const int* dst_ro = (const int*)d_in[13];
    const int* src_ao = (const int*)d_in[14];
    const int* dst_ao = (const int*)d_in[15];
    float* out = (float*)d_out;

    static cudaStream_t s1 = nullptr;
    static cudaEvent_t ev_fork = nullptr, ev_join = nullptr;
    static cudaEvent_t evA1[4], evA2[4], evG1 = nullptr, evFin = nullptr;
    if (!s1) {
        cudaStreamCreateWithFlags(&s1, cudaStreamNonBlocking);
        cudaEventCreateWithFlags(&ev_fork, cudaEventDisableTiming);
        cudaEventCreateWithFlags(&ev_join, cudaEventDisableTiming);
        cudaEventCreateWithFlags(&evG1,  cudaEventDisableTiming);
        cudaEventCreateWithFlags(&evFin, cudaEventDisableTiming);
        for (int i = 0; i < 4; i++) {
            cudaEventCreateWithFlags(&evA1[i], cudaEventDisableTiming);
            cudaEventCreateWithFlags(&evA2[i], cudaEventDisableTiming);
        }
        cudaFuncSetAttribute(gemm1, cudaFuncAttributeMaxDynamicSharedMemorySize, SMEM1_BYTES);
        cudaFuncSetAttribute(gemm2, cudaFuncAttributeMaxDynamicSharedMemorySize, SMEM2_BYTES);
    }

    const int ETOT = EOO + ERO + EAO;
    const int RB[5] = {0, 5120, 10240, 15360, 20096};  // chunk row boundaries

    // fork: prep (fp16 converts) concurrent with CSR build
    cudaEventRecord(ev_fork, 0);
    cudaStreamWaitEvent(s1, ev_fork, 0);
    prep<<<1024, 256, 0, s1>>>(W1i, W1b, W2, feat_obj, feat_room, feat_attr);
    cudaEventRecord(ev_join, s1);

    deg_all<<<(ETOT + 255) / 256, 256>>>(src_oo, dst_oo, src_ro, dst_ro, src_ao, dst_ao);
    scan3<<<3, 1024>>>();
    scatter_all<<<(ETOT + 255) / 256, 256>>>(src_oo, dst_oo, src_ro, dst_ro, src_ao, dst_ao);

    cudaStreamWaitEvent(0, ev_join, 0);

    // phase 1 pipeline: agg1 chunks (stream 0) -> gemm1 chunks (s1)
    for (int i = 0; i < 4; i++) {
        int rows = min(RB[i + 1], N_OBJ) - RB[i];
        agg1_all<<<dim3(rows, 3), 128>>>(RB[i]);
        cudaEventRecord(evA1[i], 0);
        cudaStreamWaitEvent(s1, evA1[i], 0);
        gemm1<<<dim3(4, (RB[i + 1] - RB[i]) / 64), 256, SMEM1_BYTES, s1>>>(b1i, b1b, RB[i]);
    }
    cudaEventRecord(evG1, s1);
    cudaStreamWaitEvent(0, evG1, 0);

    // phase 2 pipeline: agg2 chunks (stream 0) -> gemm2 chunks (s1)
    for (int i = 0; i < 4; i++) {
        int rows = min(RB[i + 1], N_OBJ) - RB[i];
        agg2<<<rows, 128>>>(RB[i]);
        cudaEventRecord(evA2[i], 0);
        cudaStreamWaitEvent(s1, evA2[i], 0);
        gemm2<<<dim3(4, (RB[i + 1] - RB[i]) / 128), 256, SMEM2_BYTES, s1>>>(b2, out, RB[i]);
    }
    cudaEventRecord(evFin, s1);
    cudaStreamWaitEvent(0, evFin, 0);
}

// round 17
// speedup vs baseline: 1.5238x; 1.5238x over previous
#include <cuda_runtime.h>
#include <cuda_fp16.h>
#include <cstdint>

#define N_OBJ  20000
#define N_ROOM 500
#define N_ATTR 2000
#define IN_F   300
#define HDIM   512
#define EOO    640000
#define ERO    50000
#define EAO    100000
#define BATCH  8

#define MP   20096
#define KP1  320           // conv1 K padded to 32-multiple
#define KP2  512
#define TT1  30            // 3 relations * 10 chunks of BK=32
#define TT2  16            // 512/32

// ---------------- scratch (device globals, no allocation) ----------------
__device__ __half g_hs[(size_t)N_OBJ * HDIM];     // fp16 h_obj * ns_oo

__device__ __half g_fo16[(size_t)N_OBJ  * IN_F];  // fp16 feature tables
__device__ __half g_fr16[(size_t)N_ROOM * IN_F];
__device__ __half g_fa16[(size_t)N_ATTR * IN_F];

__device__ int g_dout_oo[N_OBJ];
__device__ int g_din_oo [N_OBJ];
__device__ int g_dout_ro[N_ROOM];
__device__ int g_din_ro [N_OBJ];
__device__ int g_dout_ao[N_ATTR];
__device__ int g_din_ao [N_OBJ];

__device__ int g_off_oo[N_OBJ + 1];
__device__ int g_off_ro[N_OBJ + 1];
__device__ int g_off_ao[N_OBJ + 1];
__device__ int g_cnt_oo[N_OBJ];
__device__ int g_cnt_ro[N_OBJ];
__device__ int g_cnt_ao[N_OBJ];
__device__ int g_csr_oo[EOO];
__device__ int g_csr_ro[ERO];
__device__ int g_csr_ao[EAO];

__device__ __half g_A1[3][(size_t)MP * KP1];      // single fp16 activations
__device__ __half g_A2[(size_t)MP * KP2];
__device__ __half g_W[3][(size_t)KP2 * HDIM];     // 0:W1i 1:W1b 2:W2

// ---------------- prep: zero degs + pads + fp16 converts ----------
__global__ void prep(const float* __restrict__ W1i, const float* __restrict__ W1b,
                     const float* __restrict__ W2,
                     const float* __restrict__ fo, const float* __restrict__ fr,
                     const float* __restrict__ fa) {
    int tid    = blockIdx.x * blockDim.x + threadIdx.x;
    int stride = gridDim.x * blockDim.x;
    for (int i = tid; i < N_OBJ; i += stride) {
        g_dout_oo[i] = 0; g_din_oo[i] = 0; g_din_ro[i] = 0; g_din_ao[i] = 0;
    }
    for (int i = tid; i < N_ROOM; i += stride) g_dout_ro[i] = 0;
    for (int i = tid; i < N_ATTR; i += stride) g_dout_ao[i] = 0;
    const __half z = __float2half(0.f);
    // K-pad cols 304..319 (agg1 writes only 0..303)
    for (int i = tid; i < MP * 16; i += stride) {
        int r = i / 16, c = 304 + (i % 16);
        size_t o = (size_t)r * KP1 + c;
        g_A1[0][o] = z; g_A1[1][o] = z; g_A1[2][o] = z;
    }
    int padA1 = (MP - N_OBJ) * KP1;
    for (int i = tid; i < padA1; i += stride) {
        size_t o = (size_t)N_OBJ * KP1 + i;
        g_A1[0][o] = z; g_A1[1][o] = z; g_A1[2][o] = z;
    }
    int padA2 = (MP - N_OBJ) * KP2;
    for (int i = tid; i < padA2; i += stride)
        g_A2[(size_t)N_OBJ * KP2 + i] = z;

    const int n1 = KP1 * HDIM;
    for (int idx = tid; idx < n1; idx += stride) {
        int r = idx / HDIM;
        g_W[0][idx] = __float2half_rn((r < IN_F) ? W1i[idx] : 0.f);
        g_W[1][idx] = __float2half_rn((r < IN_F) ? W1b[idx] : 0.f);
    }
    const int n2 = KP2 * HDIM;
    for (int idx = tid; idx < n2; idx += stride)
        g_W[2][idx] = __float2half_rn(W2[idx]);

    const int nfo = N_OBJ * IN_F;
    for (int idx = tid; idx < nfo; idx += stride) g_fo16[idx] = __float2half_rn(fo[idx]);
    const int nfr = N_ROOM * IN_F;
    for (int idx = tid; idx < nfr; idx += stride) g_fr16[idx] = __float2half_rn(fr[idx]);
    const int nfa = N_ATTR * IN_F;
    for (int idx = tid; idx < nfa; idx += stride) g_fa16[idx] = __float2half_rn(fa[idx]);
}

// ---------------- merged degree counting ----------------
__global__ void deg_all(const int* __restrict__ src_oo, const int* __restrict__ dst_oo,
                        const int* __restrict__ src_ro, const int* __restrict__ dst_ro,
                        const int* __restrict__ src_ao, const int* __restrict__ dst_ao) {
    int i = blockIdx.x * blockDim.x + threadIdx.x;
    if (i < EOO) {
        atomicAdd(&g_dout_oo[src_oo[i]], 1);
        atomicAdd(&g_din_oo [dst_oo[i]], 1);
    } else if (i < EOO + ERO) {
        int j = i - EOO;
        atomicAdd(&g_dout_ro[src_ro[j]], 1);
        atomicAdd(&g_din_ro [dst_ro[j]], 1);
    } else if (i < EOO + ERO + EAO) {
        int j = i - EOO - ERO;
        atomicAdd(&g_dout_ao[src_ao[j]], 1);
        atomicAdd(&g_din_ao [dst_ao[j]], 1);
    }
}

// ---------------- 3-block exclusive scan ----------------
__global__ void scan3() {
    int sel = blockIdx.x;
    const int* deg = (sel == 0) ? g_din_oo : (sel == 1) ? g_din_ro : g_din_ao;
    int* offs      = (sel == 0) ? g_off_oo : (sel == 1) ? g_off_ro : g_off_ao;
    int* cnt       = (sel == 0) ? g_cnt_oo : (sel == 1) ? g_cnt_ro : g_cnt_ao;
    __shared__ int part[1025];
    const int n = N_OBJ;
    int t = threadIdx.x;
    int chunk = (n + 1023) / 1024;
    int b = t * chunk, e = min(b + chunk, n);
    int s = 0;
    for (int i = b; i < e; i++) s += deg[i];
    part[t + 1] = s;
    if (t == 0) part[0] = 0;
    __syncthreads();
    for (int off = 1; off < 1024; off <<= 1) {
        int v = part[t + 1];
        if (t + 1 > off) v += part[t + 1 - off];
        __syncthreads();
        part[t + 1] = v;
        __syncthreads();
    }
    int run = part[t];
    for (int i = b; i < e; i++) { offs[i] = run; cnt[i] = run; run += deg[i]; }
    if (t == 0) offs[n] = part[1024];
}

// ---------------- merged edge scatter ----------------
__global__ void scatter_all(const int* __restrict__ src_oo, const int* __restrict__ dst_oo,
                            const int* __restrict__ src_ro, const int* __restrict__ dst_ro,
                            const int* __restrict__ src_ao, const int* __restrict__ dst_ao) {
    int i = blockIdx.x * blockDim.x + threadIdx.x;
    if (i < EOO) {
        int pos = atomicAdd(&g_cnt_oo[dst_oo[i]], 1);
        g_csr_oo[pos] = src_oo[i];
    } else if (i < EOO + ERO) {
        int j = i - EOO;
        int pos = atomicAdd(&g_cnt_ro[dst_ro[j]], 1);
        g_csr_ro[pos] = src_ro[j];
    } else if (i < EOO + ERO + EAO) {
        int j = i - EOO - ERO;
        int pos = atomicAdd(&g_cnt_ao[dst_ao[j]], 1);
        g_csr_ao[pos] = src_ao[j];
    }
}

// ---------------- conv1 aggregation (fp16 features, fp32 accum) -------
__global__ void __launch_bounds__(128) agg1_all() {
    int sel = blockIdx.y;
    const __half* feat = (sel == 0) ? g_fo16 : (sel == 1) ? g_fr16 : g_fa16;
    const int* offs   = (sel == 0) ? g_off_oo  : (sel == 1) ? g_off_ro  : g_off_ao;
    const int* csr    = (sel == 0) ? g_csr_oo  : (sel == 1) ? g_csr_ro  : g_csr_ao;
    const int* degout = (sel == 0) ? g_dout_oo : (sel == 1) ? g_dout_ro : g_dout_ao;
    __half* A = g_A1[sel];

    int row = blockIdx.x;
    int t = threadIdx.x;
    int beg = offs[row], end = offs[row + 1];
    float4 a = make_float4(0.f, 0.f, 0.f, 0.f);
    __shared__ int   ss[128];
    __shared__ float sn[128];

    const int NV = IN_F / 4;            // 75
    for (int base = beg; base < end; base += 128) {
        int nB = min(128, end - base);
        __syncthreads();
        if (t < nB) {
            int s = csr[base + t];
            ss[t] = s;
            sn[t] = rsqrtf((float)max(degout[s], 1));
        }
        __syncthreads();
        int j = 0;
        if (t < NV) {
            for (; j + 4 <= nB; j += 4) {
                const uint2* p0 = (const uint2*)(feat + (size_t)ss[j + 0] * IN_F);
                const uint2* p1 = (const uint2*)(feat + (size_t)ss[j + 1] * IN_F);
                const uint2* p2 = (const uint2*)(feat + (size_t)ss[j + 2] * IN_F);
                const uint2* p3 = (const uint2*)(feat + (size_t)ss[j + 3] * IN_F);
                uint2 u0 = p0[t], u1 = p1[t], u2 = p2[t], u3 = p3[t];
                float n0 = sn[j], n1 = sn[j + 1], n2 = sn[j + 2], n3 = sn[j + 3];
                float2 c0 = __half22float2(*(__half2*)&u0.x), d0 = __half22float2(*(__half2*)&u0.y);
                float2 c1 = __half22float2(*(__half2*)&u1.x), d1 = __half22float2(*(__half2*)&u1.y);
                float2 c2 = __half22float2(*(__half2*)&u2.x), d2 = __half22float2(*(__half2*)&u2.y);
                float2 c3 = __half22float2(*(__half2*)&u3.x), d3 = __half22float2(*(__half2*)&u3.y);
                a.x += c0.x * n0 + c1.x * n1 + c2.x * n2 + c3.x * n3;
                a.y += c0.y * n0 + c1.y * n1 + c2.y * n2 + c3.y * n3;
                a.z += d0.x * n0 + d1.x * n1 + d2.x * n2 + d3.x * n3;
                a.w += d0.y * n0 + d1.y * n1 + d2.y * n2 + d3.y * n3;
            }
            for (; j < nB; j++) {
                uint2 u = ((const uint2*)(feat + (size_t)ss[j] * IN_F))[t];
                float n = sn[j];
                float2 c = __half22float2(*(__half2*)&u.x), d = __half22float2(*(__half2*)&u.y);
                a.x += c.x * n; a.y += c.y * n; a.z += d.x * n; a.w += d.y * n;
            }
        }
    }

    if (t <= NV) {
        if (t == NV) a = make_float4(0.f, 0.f, 0.f, 0.f);
        size_t o = (size_t)row * KP1 + t * 4;
        *(__half2*)(A + o)     = __floats2half2_rn(a.x, a.y);
        *(__half2*)(A + o + 2) = __floats2half2_rn(a.z, a.w);
    }
}

// ---------------- conv2 aggregation (fp16 g_hs, fp32 accum) ----------------
__global__ void __launch_bounds__(128) agg2() {
    int row = blockIdx.x;
    int t = threadIdx.x;
    int beg = g_off_oo[row], end = g_off_oo[row + 1];
    float4 a = make_float4(0.f, 0.f, 0.f, 0.f);
    __shared__ int ss[128];

    for (int base = beg; base < end; base += 128) {
        int nB = min(128, end - base);
        __syncthreads();
        if (t < nB) ss[t] = g_csr_oo[base + t];
        __syncthreads();
        int j = 0;
        for (; j + 4 <= nB; j += 4) {
            const uint2* p0 = (const uint2*)(g_hs + (size_t)ss[j + 0] * HDIM);
            const uint2* p1 = (const uint2*)(g_hs + (size_t)ss[j + 1] * HDIM);
            const uint2* p2 = (const uint2*)(g_hs + (size_t)ss[j + 2] * HDIM);
            const uint2* p3 = (const uint2*)(g_hs + (size_t)ss[j + 3] * HDIM);
            uint2 u0 = p0[t], u1 = p1[t], u2 = p2[t], u3 = p3[t];
            float2 c0 = __half22float2(*(__half2*)&u0.x), d0 = __half22float2(*(__half2*)&u0.y);
            float2 c1 = __half22float2(*(__half2*)&u1.x), d1 = __half22float2(*(__half2*)&u1.y);
            float2 c2 = __half22float2(*(__half2*)&u2.x), d2 = __half22float2(*(__half2*)&u2.y);
            float2 c3 = __half22float2(*(__half2*)&u3.x), d3 = __half22float2(*(__half2*)&u3.y);
            a.x += c0.x + c1.x + c2.x + c3.x;
            a.y += c0.y + c1.y + c2.y + c3.y;
            a.z += d0.x + d1.x + d2.x + d3.x;
            a.w += d0.y + d1.y + d2.y + d3.y;
        }
        for (; j < nB; j++) {
            uint2 u = ((const uint2*)(g_hs + (size_t)ss[j] * HDIM))[t];
            float2 c = __half22float2(*(__half2*)&u.x), d = __half22float2(*(__half2*)&u.y);
            a.x += c.x; a.y += c.y; a.z += d.x; a.w += d.y;
        }
    }

    size_t o = (size_t)row * KP2 + t * 4;
    *(__half2*)(g_A2 + o)     = __floats2half2_rn(a.x, a.y);
    *(__half2*)(g_A2 + o + 2) = __floats2half2_rn(a.z, a.w);
}

// ---------------- GEMM primitives ----------------
__device__ __forceinline__ void cpasync16(void* smem_dst, const void* gmem_src) {
    uint32_t sa = (uint32_t)__cvta_generic_to_shared(smem_dst);
    asm volatile("cp.async.cg.shared.global [%0], [%1], 16;\n" :: "r"(sa), "l"(gmem_src));
}
__device__ __forceinline__ void cp_commit() { asm volatile("cp.async.commit_group;\n" ::: "memory"); }
template <int N>
__device__ __forceinline__ void cp_wait() { asm volatile("cp.async.wait_group %0;\n" :: "n"(N) : "memory"); }

__device__ __forceinline__ void ldsm4(uint32_t* r, const void* p) {
    uint32_t a = (uint32_t)__cvta_generic_to_shared(p);
    asm volatile("ldmatrix.sync.aligned.m8n8.x4.shared.b16 {%0,%1,%2,%3}, [%4];\n"
                 : "=r"(r[0]), "=r"(r[1]), "=r"(r[2]), "=r"(r[3]) : "r"(a));
}
__device__ __forceinline__ void ldsm4t(uint32_t* r, const void* p) {
    uint32_t a = (uint32_t)__cvta_generic_to_shared(p);
    asm volatile("ldmatrix.sync.aligned.m8n8.x4.trans.shared.b16 {%0,%1,%2,%3}, [%4];\n"
                 : "=r"(r[0]), "=r"(r[1]), "=r"(r[2]), "=r"(r[3]) : "r"(a));
}
__device__ __forceinline__ void mma_fp16(float* d, const uint32_t* a, uint32_t b0, uint32_t b1) {
    asm volatile("mma.sync.aligned.m16n8k16.row.col.f32.f16.f16.f32 "
                 "{%0,%1,%2,%3}, {%4,%5,%6,%7}, {%8,%9}, {%0,%1,%2,%3};\n"
                 : "+f"(d[0]), "+f"(d[1]), "+f"(d[2]), "+f"(d[3])
                 : "r"(a[0]), "r"(a[1]), "r"(a[2]), "r"(a[3]), "r"(b0), "r"(b1));
}

// smem stage types
typedef __half (*SA1_t)[64][40];      // gemm1: [stage][m=64][kpad 40]
typedef __half (*SA2_t)[128][40];     // gemm2: [stage][m=128][kpad 40]
typedef __half (*SB_t)[32][136];      // [stage][k][npad]
#define SMEM_A1_BYTES (3 * 64 * 40 * 2)
#define SMEM_A2_BYTES (3 * 128 * 40 * 2)
#define SMEM_B_BYTES  (3 * 32 * 136 * 2)
#define SMEM1_BYTES   (SMEM_A1_BYTES + SMEM_B_BYTES)
#define SMEM2_BYTES   (SMEM_A2_BYTES + SMEM_B_BYTES)

// ---------------- merged conv1 GEMM (64x128 tile, occupancy 2) ----------
// hs = (sum_rel relu(A_rel@W+b)/3) * ns_oo
__global__ void __launch_bounds__(256, 2) gemm1(const float* __restrict__ b1i,
                                                const float* __restrict__ b1b) {
    extern __shared__ __align__(16) char smem[];
    SA1_t sA = (SA1_t)smem;
    SB_t  sB = (SB_t)(smem + SMEM_A1_BYTES);

    int tid = threadIdx.x;
    int warp = tid >> 5, lane = tid & 31;
    int row0 = blockIdx.y * 64, col0 = blockIdx.x * 128;
    int wr = warp >> 2, wc = warp & 3;   // 2x4 warps, warp tile 32x32

    float acc[2][4][4] = {};
    float accsum[2][4][4] = {};

    int aR = tid >> 2, aC = tid & 3;      // A: 64 rows x 4x16B, one pass
    int bR = tid >> 4, bC = tid & 15;     // B: 16 rows/pass x 16x16B, two passes

    auto load_stage = [&](int t, int s) {
        int rel = t / 10;
        int tt  = t % 10;
        int wsel = (rel == 2) ? 1 : 0;
        const __half* Ap = g_A1[rel];
        int kb = tt * 32;
        cpasync16(&sA[s][aR][aC * 8],
                  Ap + (size_t)(row0 + aR) * KP1 + kb + aC * 8);
        #pragma unroll
        for (int rr = 0; rr < 2; rr++)
            cpasync16(&sB[s][bR + rr * 16][bC * 8],
                      g_W[wsel] + (size_t)(kb + bR + rr * 16) * HDIM + col0 + bC * 8);
    };

    load_stage(0, 0); cp_commit();
    load_stage(1, 1); cp_commit();

    int s = 0;
    for (int t = 0; t < TT1; t++) {
        cp_wait<1>();
        __syncthreads();
        int tp = t + 2;
        if (tp < TT1) load_stage(tp, tp % 3);
        cp_commit();

        int arow = wr * 32 + (lane & 15);
        int acol8 = (lane >> 4) * 8;
        int brow = lane & 15;
        int bcol = wc * 32 + (lane >> 4) * 8;
        #pragma unroll
        for (int ksub = 0; ksub < 2; ksub++) {
            uint32_t aa[2][4], bb[2][4];
            #pragma unroll
            for (int m = 0; m < 2; m++)
                ldsm4(aa[m], &sA[s][arow + m * 16][ksub * 16 + acol8]);
            #pragma unroll
            for (int p = 0; p < 2; p++)
                ldsm4t(bb[p], &sB[s][ksub * 16 + brow][bcol + p * 16]);
            #pragma unroll
            for (int m = 0; m < 2; m++)
                #pragma unroll
                for (int n = 0; n < 4; n++) {
                    int p = n >> 1, h = n & 1;
                    mma_fp16(acc[m][n], aa[m], bb[p][h * 2], bb[p][h * 2 + 1]);
                }
        }

        if (t % 10 == 9) {
            int rel = t / 10;
            const int* degin = (rel == 0) ? g_din_oo : (rel == 1) ? g_din_ro : g_din_ao;
            const float* bias = (rel == 2) ? b1b : b1i;
            const float third = 1.f / 3.f;
            #pragma unroll
            for (int m = 0; m < 2; m++) {
                int r1 = row0 + wr * 32 + m * 16 + (lane >> 2);
                int r2 = r1 + 8;
                float nd1 = (r1 < N_OBJ) ? rsqrtf((float)max(degin[r1], 1)) : 0.f;
                float nd2 = (r2 < N_OBJ) ? rsqrtf((float)max(degin[r2], 1)) : 0.f;
                #pragma unroll
                for (int n = 0; n < 4; n++) {
                    int c = col0 + wc * 32 + n * 8 + (lane & 3) * 2;
                    float bx = bias[c], by = bias[c + 1];
                    accsum[m][n][0] += fmaxf(acc[m][n][0] * nd1 + bx, 0.f) * third;
                    accsum[m][n][1] += fmaxf(acc[m][n][1] * nd1 + by, 0.f) * third;
                    accsum[m][n][2] += fmaxf(acc[m][n][2] * nd2 + bx, 0.f) * third;
                    accsum[m][n][3] += fmaxf(acc[m][n][3] * nd2 + by, 0.f) * third;
                    acc[m][n][0] = 0.f; acc[m][n][1] = 0.f;
                    acc[m][n][2] = 0.f; acc[m][n][3] = 0.f;
                }
            }
        }
        s++; if (s == 3) s = 0;
    }

    // final write: hs = accsum * ns_oo  (fp16)
    #pragma unroll
    for (int m = 0; m < 2; m++) {
        int r1 = row0 + wr * 32 + m * 16 + (lane >> 2);
        int r2 = r1 + 8;
        float sc1 = (r1 < N_OBJ) ? rsqrtf((float)max(g_dout_oo[r1], 1)) : 0.f;
        float sc2 = (r2 < N_OBJ) ? rsqrtf((float)max(g_dout_oo[r2], 1)) : 0.f;
        #pragma unroll
        for (int n = 0; n < 4; n++) {
            int c = col0 + wc * 32 + n * 8 + (lane & 3) * 2;
            if (r1 < N_OBJ)
                *(__half2*)(g_hs + (size_t)r1 * HDIM + c) =
                    __floats2half2_rn(accsum[m][n][0] * sc1, accsum[m][n][1] * sc1);
            if (r2 < N_OBJ)
                *(__half2*)(g_hs + (size_t)r2 * HDIM + c) =
                    __floats2half2_rn(accsum[m][n][2] * sc2, accsum[m][n][3] * sc2);
        }
    }
}

// ---------------- conv2 GEMM (128x128, occupancy 2): out[b] = A2@W2*nd + b2 --
__global__ void __launch_bounds__(256, 2) gemm2(const float* __restrict__ bias,
                                                float* __restrict__ outp) {
    extern __shared__ __align__(16) char smem[];
    SA2_t sA = (SA2_t)smem;
    SB_t  sB = (SB_t)(smem + SMEM_A2_BYTES);

    int tid = threadIdx.x;
    int warp = tid >> 5, lane = tid & 31;
    int row0 = blockIdx.y * 128, col0 = blockIdx.x * 128;
    int wr = warp >> 2, wc = warp & 3;

    float acc[4][4][4] = {};

    int aR = tid >> 2, aC = tid & 3;
    int bR = tid >> 4, bC = tid & 15;

    auto load_stage = [&](int t, int s) {
        int kb = t * 32;
        #pragma unroll
        for (int rr = 0; rr < 2; rr++) {
            cpasync16(&sA[s][aR + rr * 64][aC * 8],
                      g_A2 + (size_t)(row0 + aR + rr * 64) * KP2 + kb + aC * 8);
            cpasync16(&sB[s][bR + rr * 16][bC * 8],
                      g_W[2] + (size_t)(kb + bR + rr * 16) * HDIM + col0 + bC * 8);
        }
    };

    load_stage(0, 0); cp_commit();
    load_stage(1, 1); cp_commit();

    int s = 0;
    for (int t = 0; t < TT2; t++) {
        cp_wait<1>();
        __syncthreads();
        int tp = t + 2;
        if (tp < TT2) load_stage(tp, tp % 3);
        cp_commit();

        int arow = wr * 64 + (lane & 15);
        int acol8 = (lane >> 4) * 8;
        int brow = lane & 15;
        int bcol = wc * 32 + (lane >> 4) * 8;
        #pragma unroll
        for (int ksub = 0; ksub < 2; ksub++) {
            uint32_t aa[4][4], bb[2][4];
            #pragma unroll
            for (int m = 0; m < 4; m++)
                ldsm4(aa[m], &sA[s][arow + m * 16][ksub * 16 + acol8]);
            #pragma unroll
            for (int p = 0; p < 2; p++)
                ldsm4t(bb[p], &sB[s][ksub * 16 + brow][bcol + p * 16]);
            #pragma unroll
            for (int m = 0; m < 4; m++)
                #pragma unroll
                for (int n = 0; n < 4; n++) {
                    int p = n >> 1, h = n & 1;
                    mma_fp16(acc[m][n], aa[m], bb[p][h * 2], bb[p][h * 2 + 1]);
                }
        }
        s++; if (s == 3) s = 0;
    }

    // epilogue: streaming stores (output never re-read; keep L2 for A2/W2)
    #pragma unroll
    for (int m = 0; m < 4; m++) {
        int r1 = row0 + wr * 64 + m * 16 + (lane >> 2);
        int r2 = r1 + 8;
        float nd1 = (r1 < N_OBJ) ? rsqrtf((float)max(g_din_oo[r1], 1)) : 0.f;
        float nd2 = (r2 < N_OBJ) ? rsqrtf((float)max(g_din_oo[r2], 1)) : 0.f;
        #pragma unroll
        for (int n = 0; n < 4; n++) {
            int c = col0 + wc * 32 + n * 8 + (lane & 3) * 2;
            float bx = bias[c], by = bias[c + 1];
            float2 v1 = make_float2(acc[m][n][0] * nd1 + bx, acc[m][n][1] * nd1 + by);
            float2 v2 = make_float2(acc[m][n][2] * nd2 + bx, acc[m][n][3] * nd2 + by);
            #pragma unroll
            for (int b = 0; b < BATCH; b++) {
                if (r1 < N_OBJ)
                    __stcs((float2*)(outp + (size_t)b * N_OBJ * HDIM + (size_t)r1 * HDIM + c), v1);
                if (r2 < N_OBJ)
                    __stcs((float2*)(outp + (size_t)b * N_OBJ * HDIM + (size_t)r2 * HDIM + c), v2);
            }
        }
    }
}

// ---------------- launch ----------------
extern "C" void kernel_launch(void* const* d_in, const int* in_sizes, int n_in,
                              void* d_out, int out_size) {
    const float* feat_obj  = (const float*)d_in[1];
    const float* feat_room = (const float*)d_in[2];
    const float* feat_attr = (const float*)d_in[3];
    const float* W1i = (const float*)d_in[4];
    const float* b1i = (const float*)d_in[5];
    const float* W1b = (const float*)d_in[6];
    const float* b1b = (const float*)d_in[7];
    const float* W2  = (const float*)d_in[8];
    const float* b2  = (const float*)d_in[9];
    const int* src_oo = (const int*)d_in[10];
    const int* dst_oo = (const int*)d_in[11];
    const int* src_ro = (const int*)d_in[12];
    const int* dst_ro = (const int*)d_in[13];
    const int* src_ao = (const int*)d_in[14];
    const int* dst_ao = (const int*)d_in[15];
    float* out = (float*)d_out;

    static cudaStream_t s_side = nullptr;
    static cudaEvent_t ev_fork = nullptr, ev_join = nullptr;
    if (!s_side) {
        cudaStreamCreateWithFlags(&s_side, cudaStreamNonBlocking);
        cudaEventCreateWithFlags(&ev_fork, cudaEventDisableTiming);
        cudaEventCreateWithFlags(&ev_join, cudaEventDisableTiming);
        cudaFuncSetAttribute(gemm1, cudaFuncAttributeMaxDynamicSharedMemorySize, SMEM1_BYTES);
        cudaFuncSetAttribute(gemm2, cudaFuncAttributeMaxDynamicSharedMemorySize, SMEM2_BYTES);
    }

    const int ETOT = EOO + ERO + EAO;

    // fork: prep (fp16 converts) concurrent with CSR build
    cudaEventRecord(ev_fork, 0);
    cudaStreamWaitEvent(s_side, ev_fork, 0);
    prep<<<1024, 256, 0, s_side>>>(W1i, W1b, W2, feat_obj, feat_room, feat_attr);
    cudaEventRecord(ev_join, s_side);

    deg_all<<<(ETOT + 255) / 256, 256>>>(src_oo, dst_oo, src_ro, dst_ro, src_ao, dst_ao);
    scan3<<<3, 1024>>>();
    scatter_all<<<(ETOT + 255) / 256, 256>>>(src_oo, dst_oo, src_ro, dst_ro, src_ao, dst_ao);

    cudaStreamWaitEvent(0, ev_join, 0);

    agg1_all<<<dim3(N_OBJ, 3), 128>>>();

    gemm1<<<dim3(4, MP / 64), 256, SMEM1_BYTES>>>(b1i, b1b);

    agg2<<<N_OBJ, 128>>>();

    gemm2<<<dim3(4, MP / 128), 256, SMEM2_BYTES>>>(b2, out);
}